// round 16
// baseline (speedup 1.0000x reference)
#include <cuda_runtime.h>

#define BATCH 64
#define NN 512
#define NDIAG 1023
#define NEGV  (-1e30f)
#define INV_LN2 1.44269504088896340736f
#define LN2F    0.69314718055994530942f
#define SSTR 20     // stage row stride in floats (16 used)
#define STAGE_ELEMS (4 * 256 * SSTR)
#define DP_SMEM_BYTES (STAGE_ELEMS * 4 + 2 * 257 * 8 + 4 * 9 * 8)

// Diagonal-major layout for DP outputs: (k, i) -> k*NN + i.
__device__ float g_f[(size_t)BATCH * NDIAG * NN];      // forward DP (log2 domain)
__device__ float g_b[(size_t)BATCH * NDIAG * NN];      // backward DP MINUS d (log2)
__device__ float g_max;                                // global logit max (log2)

__device__ __forceinline__ float ex2f(float x) {
    float y; asm("ex2.approx.ftz.f32 %0, %1;" : "=f"(y) : "f"(x)); return y;
}
__device__ __forceinline__ float lg2f(float x) {
    float y; asm("lg2.approx.ftz.f32 %0, %1;" : "=f"(y) : "f"(x)); return y;
}

__device__ __forceinline__ float lse_cell(float dg, float up, float lf, float dcur) {
    float hi1 = fmaxf(dg, up);
    float lo1 = fminf(dg, up);
    float m   = fmaxf(hi1, lf);
    float o2  = fminf(hi1, lf);
    float s = ex2f(lo1 - m) + ex2f(o2 - m);   // third term is 2^0 = 1
    return dcur + m + lg2f(1.0f + s);
}

// ---------------------------------------------------------------------------
// Cooperative stage loader: for round base diag kbase, fetch d(i, kbase+p-i)
// for all 512 rows x 8 phases, scaled by 1/ln2. 8 lanes per row -> coalesced.
// Out-of-range cols clamp in-allocation; consumed only by invalid cells.
// ---------------------------------------------------------------------------
template<bool BWD>
__device__ __forceinline__ void stage_fetch(const float* __restrict__ Db,
                                            int kbase, int t, float* vals) {
    int p = t & 7;
    int r0 = t >> 3;            // 0..31
#pragma unroll
    for (int q = 0; q < 16; q++) {
        int r = r0 + 32 * q;    // DP row
        int c = kbase + p - r;  // DP col
        int rg = BWD ? (511 - r) : r;
        int cg = BWD ? (511 - c) : c;
        cg = min(max(cg, 0), 511);
        vals[q] = Db[rg * NN + cg] * INV_LN2;
    }
}

// Transposed stage: value for (row r, phase lp) at stageT[r>>1][2*lp + (r&1)],
// so consumer thread t = r>>1 reads a phase-pair's 4 values as one LDS.128.
__device__ __forceinline__ void stage_put(float (*stageT)[SSTR], int t,
                                          const float* vals) {
    int lp = t & 7, lr = t >> 3;
#pragma unroll
    for (int q = 0; q < 16; q++) {
        int r = lr + 32 * q;
        stageT[r >> 1][2 * lp + (r & 1)] = vals[q];
    }
}

// ---------------------------------------------------------------------------
// Wavefront DP, TWO diagonals per barrier via warp skew (no redundant work).
// 256 threads, thread t owns rows (2t, 2t+1); warp w owns rows [64w, 64w+64)
// and at phase r computes diags ka = 2r-2w and ka+1.
//  - odd-row cells: all-register inputs
//  - even cell @ka: nb pair (vO(ka-2), vO(ka-1)) of thread t-1 via one LDS.64
//    from a parity buffer (published last phase)
//  - even cell @ka+1: vO(ka) of thread t-1 via one same-phase __shfl_up
//  - lane 0: values cross warps through a 4-slot phase-ring edge array
//    written by warp w-1 one/two phases earlier (barrier-ordered; reader
//    slots (r-1)&3, (r-2)&3 never equal writer slot r&3)
// D from the transposed stage, 4-slot ring (fill phase 4m, put 4m+3; put of
// round R at phase 4R-5 never collides with readers: last read of the slot's
// old round R-4 is at phase 4R-6). One LDS.128 per thread per phase.
// Backward CTAs write (val - d). Per-cell math identical to prior rounds.
// ---------------------------------------------------------------------------
template<bool BWD>
__device__ __forceinline__ void dp_impl(int b, const float* __restrict__ D,
                                        float* smem) {
    const float* Db = D + (size_t)b * NN * NN;
    float* out = (BWD ? g_b : g_f) + (size_t)b * NDIAG * NN;
    int t = threadIdx.x, lane = t & 31, w = t >> 5;
    int iE = 2 * t;
    float (*stageT)[256][SSTR] = (float(*)[256][SSTR])smem;
    float2* nb2  = (float2*)(smem + STAGE_ELEMS);   // [2][257], slot0 = NEG
    float2* edge = nb2 + 2 * 257;                   // [4][9],  [.,0] = NEG

    float vals[16];
    {   // preloop: rounds 0,1 staged; round 2 held in regs
        float v[16];
        stage_fetch<BWD>(Db, 0, t, v);  stage_put(stageT[0], t, v);
        stage_fetch<BWD>(Db, 8, t, v);  stage_put(stageT[1], t, v);
        stage_fetch<BWD>(Db, 16, t, vals);
    }
    __syncthreads();   // covers nb2/edge init (in caller) + stage puts

    float vE1 = NEGV, vE2 = NEGV, vO1 = NEGV, vO2 = NEGV;

    for (int rr = 0; rr < 130; rr++) {
#pragma unroll
        for (int q = 0; q < 4; q++) {
            int r = 4 * rr + q;
            if (q == 0 && rr > 0)
                stage_fetch<BWD>(Db, 8 * (rr + 2), t, vals);
            int ka = 2 * r - 2 * w;
            if ((unsigned)ka <= 1022u) {
                int p = ka & 7;
                const float4 d4 =
                    *(const float4*)&stageT[(ka >> 3) & 3][t][2 * p];
                float2 nb = nb2[((q + 1) & 1) * 257 + t];
                float e1x = NEGV;
                if (lane == 0) {
                    nb  = edge[((q + 2) & 3) * 9 + w];      // (vO(ka-2), vO(ka-1))
                    e1x = edge[((q + 3) & 3) * 9 + w].x;    // vO(ka)
                }
                // diag ka, even cell (iE, ka-iE)
                float dgE = nb.x;
                if (ka == 0 && t == 0) dgE = 0.0f;          // (0,0) seed
                float vE = lse_cell(dgE, nb.y, vE1, d4.x);
                unsigned jE = (unsigned)(ka - iE);
                vE = (jE < NN) ? vE : NEGV;
                // diag ka, odd cell (iE+1, ka-1-iE): registers only
                float vO = lse_cell(vE2, vE1, vO1, d4.y);
                vO = (jE - 1u < NN) ? vO : NEGV;
                if (jE <= NN)
                    *(float2*)(out + (size_t)ka * NN + iE) =
                        make_float2(BWD ? vE - d4.x : vE,
                                    BWD ? vO - d4.y : vO);
                // neighbor's vO(ka): same-phase shfl (lane0 from edge)
                float upn = __shfl_up_sync(0xffffffffu, vO, 1);
                if (lane == 0) upn = e1x;
                // diag ka+1, even cell (iE, ka+1-iE)
                float vEb = lse_cell(nb.y, upn, vE, d4.z);
                vEb = (jE + 1u < NN) ? vEb : NEGV;
                // diag ka+1, odd cell (iE+1, ka-iE): registers only
                float vOb = lse_cell(vE1, vE, vO, d4.w);
                vOb = (jE < NN) ? vOb : NEGV;
                if (jE + 1u <= NN)
                    *(float2*)(out + (size_t)(ka + 1) * NN + iE) =
                        make_float2(BWD ? vEb - d4.z : vEb,
                                    BWD ? vOb - d4.w : vOb);
                // publish for next phase / warp below
                nb2[(q & 1) * 257 + 1 + t] = make_float2(vO, vOb);
                if (lane == 31)
                    edge[(q & 3) * 9 + w + 1] = make_float2(vO, vOb);
                vE2 = vE; vE1 = vEb; vO2 = vO; vO1 = vOb;
            }
            if (q == 3)
                stage_put(stageT[(rr + 2) & 3], t, vals);
            __syncthreads();
        }
    }
}

__global__ void __launch_bounds__(256) dp_kernel(const float* __restrict__ D) {
    extern __shared__ float smem_dp[];
    int bx = blockIdx.x;
    int b = bx >> 1, dir = bx & 1;
    // init nb2 + edge to NEGV (stage needs no init; preloop fills it)
    float* initp = smem_dp + STAGE_ELEMS;
    for (int qq = threadIdx.x; qq < 2 * 257 * 2 + 4 * 9 * 2; qq += 256)
        initp[qq] = NEGV;
    if (dir) dp_impl<true>(b, D, smem_dp);
    else     dp_impl<false>(b, D, smem_dp);
}

// ---------------------------------------------------------------------------
// Global max: every path passes through the corner cell, so
// max logit = f(N-1, M-1) maximized over batches.
// ---------------------------------------------------------------------------
__global__ void max_kernel() {
    int t = threadIdx.x;   // 32 threads
    float m = -3.4e38f;
    for (int b = t; b < BATCH; b += 32)
        m = fmaxf(m, g_f[(size_t)b * NDIAG * NN + (size_t)1022 * NN + 511]);
#pragma unroll
    for (int o = 16; o > 0; o >>= 1)
        m = fmaxf(m, __shfl_xor_sync(0xffffffffu, m, o));
    if (t == 0) g_max = m;
}

// ---------------------------------------------------------------------------
// Combine + finish fused: out = (f2 + (b2-d2) - max2) * ln2, de-diagonalized
// to row-major via a padded smem tile.
// ---------------------------------------------------------------------------
__global__ void __launch_bounds__(256) combine_kernel(float* __restrict__ out) {
    __shared__ float tile[32][257];
    int b = blockIdx.y;
    int k0 = blockIdx.x * 32;
    const float* fd = g_f + (size_t)b * NDIAG * NN;
    const float* bd = g_b + (size_t)b * NDIAG * NN;
    float* ob = out + (size_t)b * NN * NN;
    int tid = threadIdx.x, lane = tid & 31, w = tid >> 5;
    float mx = g_max;

    for (int ih = 0; ih < 2; ih++) {
        int ibase = ih * 256;
        for (int kk = 0; kk < 32; kk++) {
            int k = k0 + kk;
            int i = ibase + tid;
            int j = k - i;
            float v = 0.0f;
            if (j >= 0 && j < NN) {
                int a = k * NN + i;
                v = (fd[a] + bd[(1022 - k) * NN + (511 - i)] - mx) * LN2F;
            }
            tile[kk][tid] = v;
        }
        __syncthreads();
        for (int rr = 0; rr < 32; rr++) {
            int i = ibase + w * 32 + rr;
            int jlo = max(0, k0 - i);
            int jhi = min(NN - 1, k0 + 31 - i);
            int j = jlo + lane;
            if (j <= jhi) {
                int kk = i + j - k0;
                ob[(size_t)i * NN + j] = tile[kk][i - ibase];
            }
        }
        __syncthreads();
    }
}

extern "C" void kernel_launch(void* const* d_in, const int* in_sizes, int n_in,
                              void* d_out, int out_size) {
    const float* d = (const float*)d_in[0];
    float* out = (float*)d_out;

    cudaFuncSetAttribute(dp_kernel,
                         cudaFuncAttributeMaxDynamicSharedMemorySize,
                         DP_SMEM_BYTES);

    dp_kernel<<<BATCH * 2, 256, DP_SMEM_BYTES>>>(d);

    max_kernel<<<1, 32>>>();

    dim3 cgrid(32, BATCH);
    combine_kernel<<<cgrid, 256>>>(out);
}